// round 2
// baseline (speedup 1.0000x reference)
#include <cuda_runtime.h>
#include <cstdint>
#include <math.h>

// Problem constants: B=4, T=4096, C=2048, E=64, K=8
#define NTOK   16384
#define CDIM   2048
#define NEXP   64
#define KTOP   8
#define BM     64
#define BK     32
#define NKTOT  (NTOK * KTOP)

// scratch for masked expert bincount (no cudaMalloc allowed)
__device__ float g_counts[NEXP];

__global__ void k_zero_counts() {
    if (threadIdx.x < NEXP) g_counts[threadIdx.x] = 0.f;
}

// --- packed fp32x2 helpers (B300: scalar FFMA is half-rate; f32x2 is full-rate) ---
__device__ __forceinline__ unsigned long long dup2(float x) {
    unsigned long long r;
    asm("mov.b64 %0, {%1, %1};" : "=l"(r) : "f"(x));
    return r;
}
__device__ __forceinline__ void fma2(unsigned long long& d, unsigned long long a, unsigned long long b) {
    asm("fma.rn.f32x2 %0, %1, %2, %0;" : "+l"(d) : "l"(a), "l"(b));
}
__device__ __forceinline__ float2 unpack2(unsigned long long v) {
    float2 f;
    asm("mov.b64 {%0, %1}, %2;" : "=f"(f.x), "=f"(f.y) : "l"(v));
    return f;
}

// sortable key: larger value wins; ties -> smaller expert index wins (matches jax.lax.top_k)
__device__ __forceinline__ unsigned long long sortkey(float v, int e) {
    unsigned u = __float_as_uint(v);
    u = (u & 0x80000000u) ? ~u : (u | 0x80000000u);
    return ((unsigned long long)u << 32) | (unsigned)(63 - e);
}

// Fused: GEMM (x @ W^T) -> logits tile in smem -> sigmoid/top-8/normalize -> outputs + bincount.
// Grid: NTOK/BM = 256 blocks, 256 threads.
__global__ __launch_bounds__(256) void k_gate(
    const float* __restrict__ X,            // [NTOK, CDIM]
    const int* __restrict__ mask,           // [NTOK] (bool materialized as int32)
    const float* __restrict__ W,            // [NEXP, CDIM]
    const float* __restrict__ gb,           // [NEXP] gate_bias
    const float* __restrict__ eb,           // [NEXP] expert_biases
    float* __restrict__ out)                // [NKTOT idx | NKTOT probs | 1 maxvio]
{
    __shared__ float smem[8192];   // 32KB: double-buffered As/Bs, reused as logits tile
    __shared__ float sCnt[NEXP];

    float* As = smem;          // [2][BK*BM]
    float* Bs = smem + 4096;   // [2][BK*NEXP]

    const int tid = threadIdx.x;
    const int tx = tid & 15;       // expert group (4 experts)
    const int ty = tid >> 4;       // token group (4 tokens)
    const int tok0 = blockIdx.x * BM;

    if (tid < NEXP) sCnt[tid] = 0.f;

    // global load mapping: 512 float4 per tile per matrix, 2 per thread
    const int r0 = tid >> 3,         c0 = (tid & 7) * 4;
    const int r1 = (tid + 256) >> 3, c1 = ((tid + 256) & 7) * 4;
    const float* A0 = X + (size_t)(tok0 + r0) * CDIM + c0;
    const float* A1 = X + (size_t)(tok0 + r1) * CDIM + c1;
    const float* B0 = W + (size_t)r0 * CDIM + c0;
    const float* B1 = W + (size_t)r1 * CDIM + c1;

    // accumulators: token-pairs (f32x2) x 4 experts -> 16 fp32 values
    unsigned long long acc[2][4];
#pragma unroll
    for (int i = 0; i < 2; i++)
#pragma unroll
        for (int j = 0; j < 4; j++) acc[i][j] = 0ull;

    // ---- prologue: tile 0 -> buffer 0 (stored transposed: [k][m]) ----
    {
        float4 a0 = *(const float4*)A0;
        float4 a1 = *(const float4*)A1;
        float4 b0 = *(const float4*)B0;
        float4 b1 = *(const float4*)B1;
#pragma unroll
        for (int c = 0; c < 4; c++) {
            As[(c0 + c) * BM + r0] = ((const float*)&a0)[c];
            As[(c1 + c) * BM + r1] = ((const float*)&a1)[c];
            Bs[(c0 + c) * NEXP + r0] = ((const float*)&b0)[c];
            Bs[(c1 + c) * NEXP + r1] = ((const float*)&b1)[c];
        }
    }
    __syncthreads();

    const int NT = CDIM / BK;  // 64
    for (int t = 0; t < NT; t++) {
        const int cur = t & 1;
        float4 a0n, a1n, b0n, b1n;
        if (t + 1 < NT) {
            const int off = (t + 1) * BK;
            a0n = *(const float4*)(A0 + off);
            a1n = *(const float4*)(A1 + off);
            b0n = *(const float4*)(B0 + off);
            b1n = *(const float4*)(B1 + off);
        }

        const ulonglong2* Asv = (const ulonglong2*)(As + cur * 2048);
        const float4*     Bsv = (const float4*)(Bs + cur * 2048);
#pragma unroll
        for (int k = 0; k < BK; k++) {
            ulonglong2 av = Asv[k * 16 + ty];   // 4 tokens as 2 fp32x2 pairs
            float4     bv = Bsv[k * 16 + tx];   // 4 experts
            unsigned long long bd0 = dup2(bv.x), bd1 = dup2(bv.y);
            unsigned long long bd2 = dup2(bv.z), bd3 = dup2(bv.w);
            fma2(acc[0][0], av.x, bd0); fma2(acc[1][0], av.y, bd0);
            fma2(acc[0][1], av.x, bd1); fma2(acc[1][1], av.y, bd1);
            fma2(acc[0][2], av.x, bd2); fma2(acc[1][2], av.y, bd2);
            fma2(acc[0][3], av.x, bd3); fma2(acc[1][3], av.y, bd3);
        }

        if (t + 1 < NT) {
            float* Asn = As + (1 - cur) * 2048;
            float* Bsn = Bs + (1 - cur) * 2048;
#pragma unroll
            for (int c = 0; c < 4; c++) {
                Asn[(c0 + c) * BM + r0] = ((const float*)&a0n)[c];
                Asn[(c1 + c) * BM + r1] = ((const float*)&a1n)[c];
                Bsn[(c0 + c) * NEXP + r0] = ((const float*)&b0n)[c];
                Bsn[(c1 + c) * NEXP + r1] = ((const float*)&b1n)[c];
            }
            __syncthreads();
        }
    }
    __syncthreads();  // GEMM done; smem free for reuse

    // ---- write logits tile Ls[m][n], stride 65 (conflict-free column reads) ----
    float* Ls = smem;
#pragma unroll
    for (int ip = 0; ip < 2; ip++)
#pragma unroll
        for (int j = 0; j < 4; j++) {
            float2 v = unpack2(acc[ip][j]);
            const int n = tx * 4 + j;
            const float b = gb[n];
            Ls[(ty * 4 + ip * 2 + 0) * 65 + n] = v.x + b;
            Ls[(ty * 4 + ip * 2 + 1) * 65 + n] = v.y + b;
        }
    __syncthreads();

    // ---- warp-per-token top-8 of 64 ----
    const int lane = tid & 31;
    const int warp = tid >> 5;
    const float eb0 = eb[lane], eb1 = eb[lane + 32];

    for (int q = 0; q < 8; q++) {
        const int m = warp * 8 + q;
        const int tok = tok0 + m;
        const float* row = Ls + m * 65;
        const float g0 = row[lane], g1 = row[lane + 32];
        const float s0 = g0 + eb0,  s1 = g1 + eb1;   // routing logits
        bool u0 = false, u1 = false;
        float selIdx = 0.f, selProb = 0.f;
        const int mk = mask[tok];

#pragma unroll
        for (int it = 0; it < KTOP; it++) {
            unsigned long long k0 = u0 ? 0ull : sortkey(s0, lane);
            unsigned long long k1 = u1 ? 0ull : sortkey(s1, lane + 32);
            unsigned long long key = k0 > k1 ? k0 : k1;
#pragma unroll
            for (int o = 16; o; o >>= 1) {
                unsigned long long oth = __shfl_xor_sync(0xffffffffu, key, o);
                if (oth > key) key = oth;
            }
            const int e = 63 - (int)(key & 63u);
            if (e == lane)      u0 = true;
            if (e == lane + 32) u1 = true;
            if (lane == it) {
                const float g = row[e];               // gate_output (no expert_bias)
                selIdx = (float)e;
                selProb = 1.f / (1.f + expf(-g));     // sigmoid
                if (mk) atomicAdd(&sCnt[e], 1.f);
            }
        }
        float p = (lane < KTOP) ? selProb : 0.f;
        float sum = p;
#pragma unroll
        for (int o = 16; o; o >>= 1) sum += __shfl_xor_sync(0xffffffffu, sum, o);
        if (lane < KTOP) {
            out[(size_t)tok * KTOP + lane]         = selIdx;          // index as float
            out[NKTOT + (size_t)tok * KTOP + lane] = selProb / sum;   // normalized prob
        }
    }

    __syncthreads();
    if (tid < NEXP) {
        const float c = sCnt[tid];
        if (c != 0.f) atomicAdd(&g_counts[tid], c);
    }
}

__global__ void k_finalize(float* __restrict__ out, int pos) {
    const int lane = threadIdx.x;
    float c0 = g_counts[lane], c1 = g_counts[lane + 32];
    float mx = fmaxf(c0, c1);
    float sm = c0 + c1;
#pragma unroll
    for (int o = 16; o; o >>= 1) {
        mx = fmaxf(mx, __shfl_xor_sync(0xffffffffu, mx, o));
        sm += __shfl_xor_sync(0xffffffffu, sm, o);
    }
    if (lane == 0) {
        const float avg = sm / 64.f;
        out[pos] = (mx - avg) / (avg + 1e-5f);
    }
}

extern "C" void kernel_launch(void* const* d_in, const int* in_sizes, int n_in,
                              void* d_out, int out_size) {
    const float* X    = (const float*)d_in[0];
    const int*   mask = (const int*)d_in[1];
    const float* W    = (const float*)d_in[2];
    const float* gb   = (const float*)d_in[3];
    const float* eb   = (const float*)d_in[4];
    float*       out  = (float*)d_out;

    k_zero_counts<<<1, 64>>>();
    k_gate<<<NTOK / BM, 256>>>(X, mask, W, gb, eb, out);
    k_finalize<<<1, 32>>>(out, out_size - 1);
}

// round 4
// speedup vs baseline: 1.1744x; 1.1744x over previous
#include <cuda_runtime.h>
#include <cstdint>
#include <math.h>

// Problem: B=4, T=4096, C=2048, E=64, K=8
#define NTOK   16384
#define CDIM   2048
#define NEXP   64
#define KTOP   8
#define BM     128
#define BK     32
#define NCHUNK (CDIM / BK)   // 64
#define NKTOT  (NTOK * KTOP)

// smem layout (dynamic): A [2][BK][132] floats, then B [2][BK][68] floats
#define APITCH 132
#define BPITCH 68
#define ABUF   (BK * APITCH)             // 4224 floats
#define BBUF   (BK * BPITCH)             // 2176 floats
#define AREG   (2 * ABUF)                // 8448 floats
#define SMEM_DYN ((AREG + 2 * BBUF) * 4) // 51200 bytes

__device__ float g_counts[NEXP];

// --- packed fp32x2 helpers (B300: scalar FFMA is half-rate; f32x2 is full-rate) ---
__device__ __forceinline__ unsigned long long dup2(float x) {
    unsigned long long r;
    asm("mov.b64 %0, {%1, %1};" : "=l"(r) : "f"(x));
    return r;
}
__device__ __forceinline__ void fma2(unsigned long long& d, unsigned long long a, unsigned long long b) {
    asm("fma.rn.f32x2 %0, %1, %2, %0;" : "+l"(d) : "l"(a), "l"(b));
}
__device__ __forceinline__ float2 unpack2(unsigned long long v) {
    float2 f;
    asm("mov.b64 {%0, %1}, %2;" : "=f"(f.x), "=f"(f.y) : "l"(v));
    return f;
}

// larger value wins; ties -> smaller expert index (matches jax.lax.top_k)
__device__ __forceinline__ unsigned long long sortkey(float v, int e) {
    unsigned u = __float_as_uint(v);
    u = (u & 0x80000000u) ? ~u : (u | 0x80000000u);
    return ((unsigned long long)u << 32) | (unsigned)(63 - e);
}

// Fused: GEMM (x @ W^T) -> logits in smem -> sigmoid/top-8/normalize -> outputs + bincount.
// Grid: NTOK/BM = 128 blocks (single wave on 148 SMs), 256 threads.
__global__ __launch_bounds__(256, 1) void k_gate(
    const float* __restrict__ X,    // [NTOK, CDIM]
    const int* __restrict__ mask,   // [NTOK] bool as int32
    const float* __restrict__ W,    // [NEXP, CDIM]
    const float* __restrict__ gb,   // [NEXP]
    const float* __restrict__ eb,   // [NEXP]
    float* __restrict__ out)        // [NKTOT idx | NKTOT probs | 1 maxvio]
{
    extern __shared__ float smem[];        // [AREG | 2*BBUF]
    __shared__ float sGb[NEXP], sEb[NEXP], sCnt[NEXP];

    float* As = smem;                      // [2][BK][APITCH]
    float* Bs = smem + AREG;               // [2][BK][BPITCH]

    const int tid  = threadIdx.x;
    const int lane = tid & 31;
    const int wid  = tid >> 5;
    const int tx   = tid & 15;             // expert group: experts tx*4 .. +3
    const int ty   = tid >> 4;             // token group:  tokens ty*8 .. +7
    const int tok0 = blockIdx.x * BM;

    if (tid < NEXP) { sGb[tid] = gb[tid]; sEb[tid] = eb[tid]; sCnt[tid] = 0.f; }

    // global load mapping: A 1024 float4/chunk (4/thread), B 512 (2/thread)
    int ar[4], ac[4], br[2], bc[2];
    const float* Ag[4];
    const float* Bg[2];
#pragma unroll
    for (int p = 0; p < 4; p++) {
        int idx = tid + p * 256;
        ar[p] = idx >> 3; ac[p] = (idx & 7) * 4;
        Ag[p] = X + (size_t)(tok0 + ar[p]) * CDIM + ac[p];
    }
#pragma unroll
    for (int p = 0; p < 2; p++) {
        int idx = tid + p * 256;
        br[p] = idx >> 3; bc[p] = (idx & 7) * 4;
        Bg[p] = W + (size_t)br[p] * CDIM + bc[p];
    }

    // accumulators: 4 token-pairs (f32x2) x 4 experts
    unsigned long long acc[4][4];
#pragma unroll
    for (int i = 0; i < 4; i++)
#pragma unroll
        for (int j = 0; j < 4; j++) acc[i][j] = 0ull;

    // ---- prologue: chunk 0 -> buffer 0 (transposed [k][m]) ----
    {
        float4 a[4], b[2];
#pragma unroll
        for (int p = 0; p < 4; p++) a[p] = *(const float4*)Ag[p];
#pragma unroll
        for (int p = 0; p < 2; p++) b[p] = *(const float4*)Bg[p];
#pragma unroll
        for (int p = 0; p < 4; p++)
#pragma unroll
            for (int c = 0; c < 4; c++)
                As[(ac[p] + c) * APITCH + ar[p]] = ((const float*)&a[p])[c];
#pragma unroll
        for (int p = 0; p < 2; p++)
#pragma unroll
            for (int c = 0; c < 4; c++)
                Bs[(bc[p] + c) * BPITCH + br[p]] = ((const float*)&b[p])[c];
    }
    __syncthreads();

    for (int t = 0; t < NCHUNK; t++) {
        const int cur = t & 1;
        float4 an[4], bn[2];
        if (t + 1 < NCHUNK) {
            const int off = (t + 1) * BK;
#pragma unroll
            for (int p = 0; p < 4; p++) an[p] = *(const float4*)(Ag[p] + off);
#pragma unroll
            for (int p = 0; p < 2; p++) bn[p] = *(const float4*)(Bg[p] + off);
        }

        const float* Ab = As + cur * ABUF + ty * 8;
        const float* Bb = Bs + cur * BBUF + tx * 4;
#pragma unroll
        for (int k = 0; k < BK; k++) {
            ulonglong2 a01 = *(const ulonglong2*)(Ab + k * APITCH);       // tokens 0..3
            ulonglong2 a23 = *(const ulonglong2*)(Ab + k * APITCH + 4);   // tokens 4..7
            float4     bv  = *(const float4*)(Bb + k * BPITCH);           // 4 experts
            unsigned long long b0 = dup2(bv.x), b1 = dup2(bv.y);
            unsigned long long b2 = dup2(bv.z), b3 = dup2(bv.w);
            fma2(acc[0][0], a01.x, b0); fma2(acc[0][1], a01.x, b1);
            fma2(acc[0][2], a01.x, b2); fma2(acc[0][3], a01.x, b3);
            fma2(acc[1][0], a01.y, b0); fma2(acc[1][1], a01.y, b1);
            fma2(acc[1][2], a01.y, b2); fma2(acc[1][3], a01.y, b3);
            fma2(acc[2][0], a23.x, b0); fma2(acc[2][1], a23.x, b1);
            fma2(acc[2][2], a23.x, b2); fma2(acc[2][3], a23.x, b3);
            fma2(acc[3][0], a23.y, b0); fma2(acc[3][1], a23.y, b1);
            fma2(acc[3][2], a23.y, b2); fma2(acc[3][3], a23.y, b3);
        }

        if (t + 1 < NCHUNK) {
            float* Asn = As + (1 - cur) * ABUF;
            float* Bsn = Bs + (1 - cur) * BBUF;
#pragma unroll
            for (int p = 0; p < 4; p++)
#pragma unroll
                for (int c = 0; c < 4; c++)
                    Asn[(ac[p] + c) * APITCH + ar[p]] = ((const float*)&an[p])[c];
#pragma unroll
            for (int p = 0; p < 2; p++)
#pragma unroll
                for (int c = 0; c < 4; c++)
                    Bsn[(bc[p] + c) * BPITCH + br[p]] = ((const float*)&bn[p])[c];
            __syncthreads();
        }
    }
    __syncthreads();   // GEMM done; smem free for reuse

    // ---- logits tile Ls[m][n], stride 65 (conflict-free column reads), +gate_bias ----
    float* Ls = smem;
#pragma unroll
    for (int i = 0; i < 4; i++)
#pragma unroll
        for (int j = 0; j < 4; j++) {
            float2 v = unpack2(acc[i][j]);
            const int n = tx * 4 + j;
            const float b = sGb[n];
            Ls[(ty * 8 + 2 * i + 0) * 65 + n] = v.x + b;
            Ls[(ty * 8 + 2 * i + 1) * 65 + n] = v.y + b;
        }
    __syncthreads();

    // ---- warp-per-token top-8 of 64 (proven epilogue); 8 warps x 16 tokens ----
    const float eb0 = sEb[lane], eb1 = sEb[lane + 32];
    for (int q = 0; q < 16; q++) {
        const int m = wid * 16 + q;
        const int tok = tok0 + m;
        const float* row = Ls + m * 65;
        const float g0 = row[lane], g1 = row[lane + 32];
        const float s0 = g0 + eb0, s1 = g1 + eb1;
        bool u0 = false, u1 = false;
        float selIdx = 0.f, selProb = 0.f;
        const int mk = mask[tok];

#pragma unroll
        for (int it = 0; it < KTOP; it++) {
            unsigned long long k0 = u0 ? 0ull : sortkey(s0, lane);
            unsigned long long k1 = u1 ? 0ull : sortkey(s1, lane + 32);
            unsigned long long key = k0 > k1 ? k0 : k1;
#pragma unroll
            for (int o = 16; o; o >>= 1) {
                unsigned long long oth = __shfl_xor_sync(0xffffffffu, key, o);
                if (oth > key) key = oth;
            }
            const int e = 63 - (int)(key & 63u);
            if (e == lane)      u0 = true;
            if (e == lane + 32) u1 = true;
            if (lane == it) {
                const float g = row[e];
                selIdx = (float)e;
                selProb = 1.f / (1.f + expf(-g));
                if (mk) atomicAdd(&sCnt[e], 1.f);
            }
        }
        float p = (lane < KTOP) ? selProb : 0.f;
        float sum = p;
#pragma unroll
        for (int o = 16; o; o >>= 1) sum += __shfl_xor_sync(0xffffffffu, sum, o);
        if (lane < KTOP) {
            out[(size_t)tok * KTOP + lane]         = selIdx;
            out[NKTOT + (size_t)tok * KTOP + lane] = selProb / sum;
        }
    }

    __syncthreads();
    if (tid < NEXP) {
        const float c = sCnt[tid];
        if (c != 0.f) atomicAdd(&g_counts[tid], c);
    }
}

// reduce counts -> maxvio, then zero counts for the next replay (deterministic)
__global__ void k_finalize(float* __restrict__ out, int pos) {
    const int lane = threadIdx.x;
    float c0 = g_counts[lane], c1 = g_counts[lane + 32];
    float mx = fmaxf(c0, c1);
    float sm = c0 + c1;
#pragma unroll
    for (int o = 16; o; o >>= 1) {
        mx = fmaxf(mx, __shfl_xor_sync(0xffffffffu, mx, o));
        sm += __shfl_xor_sync(0xffffffffu, sm, o);
    }
    if (lane == 0) {
        const float avg = sm / 64.f;
        out[pos] = (mx - avg) / (avg + 1e-5f);
    }
    g_counts[lane] = 0.f;
    g_counts[lane + 32] = 0.f;
}

extern "C" void kernel_launch(void* const* d_in, const int* in_sizes, int n_in,
                              void* d_out, int out_size) {
    const float* X    = (const float*)d_in[0];
    const int*   mask = (const int*)d_in[1];
    const float* W    = (const float*)d_in[2];
    const float* gb   = (const float*)d_in[3];
    const float* eb   = (const float*)d_in[4];
    float*       out  = (float*)d_out;

    cudaFuncSetAttribute(k_gate, cudaFuncAttributeMaxDynamicSharedMemorySize, SMEM_DYN);
    k_gate<<<NTOK / BM, 256, SMEM_DYN>>>(X, mask, W, gb, eb, out);
    k_finalize<<<1, 32>>>(out, out_size - 1);
}